// round 16
// baseline (speedup 1.0000x reference)
#include <cuda_runtime.h>
#include <cuda_fp16.h>

#define BB 2
#define C 256
#define NH 8
#define HD 32
#define NN 4096
// 32^-0.5 * log2(e)
#define SCLOG2 0.2550348655f
#define KSTRIDE 40    // halves per K row [key][d] (20 words -> frag LDS conflict-free; 80B row)
#define VSTRIDE 136   // halves per V smem row (conflict-free)
#define PSTRIDE 72    // halves per GEMM smem row (conflict-free)
#define STAGEHALF (128 * KSTRIDE + 32 * VSTRIDE)   // 9472 halves per pipeline stage
#define VOFFB (128 * KSTRIDE * 2)                  // byte offset of V within a stage
#define ONESH2 0x3C003C00u                          // half2(1.0, 1.0)

__device__ __half g_qkv[2][BB][3][C][NN];   // fp16 Q/K/V (V stored key-permuted)
__device__ __half g_qt[2][BB][NH][NN][HD];  // Q^T per head [n][d-permuted], pre-scaled by SCLOG2
__device__ __half g_kt[2][BB][NH][NN][HD];  // K^T per head [n][d-permuted]
__device__ __half g_attn[2][BB][C][NN];     // fp16 attention outputs
__device__ __half g_wh[3][C][C];            // fp16 wq/wk/wv
__device__ __half g_wo[C][C];               // fp16 wo

// position of element k within its permuted 16-group: pairs reordered so that
// frag pairs (2tc,2tc+1) and (2tc+8,2tc+9) are adjacent (8-byte) in storage.
__device__ __forceinline__ int pk16(int k) {
    int m = k >> 1;
    int q = ((m & 3) << 1) | (m >> 2);
    return (q << 1) | (k & 1);
}

__device__ __forceinline__ unsigned h2bits(float lo, float hi) {
    __half2 h = __floats2half2_rn(lo, hi);
    return *(unsigned*)&h;
}
__device__ __forceinline__ unsigned hexp2_2(unsigned x) {
    unsigned y; asm("ex2.approx.f16x2 %0, %1;" : "=r"(y) : "r"(x)); return y;
}
__device__ __forceinline__ void cpa16(unsigned dst, const void* src) {
    asm volatile("cp.async.cg.shared.global [%0], [%1], 16;" :: "r"(dst), "l"(src));
}
__device__ __forceinline__ void mma_f16(float* d, unsigned a0, unsigned a1, unsigned a2,
                                        unsigned a3, unsigned b0, unsigned b1) {
    asm volatile(
        "mma.sync.aligned.m16n8k16.row.col.f32.f16.f16.f32 "
        "{%0,%1,%2,%3},{%4,%5,%6,%7},{%8,%9},{%0,%1,%2,%3};"
        : "+f"(d[0]), "+f"(d[1]), "+f"(d[2]), "+f"(d[3])
        : "r"(a0), "r"(a1), "r"(a2), "r"(a3), "r"(b0), "r"(b1));
}

// ---------------------------------------------------------------------------
// fp32 -> fp16 conversion: weights only (wq/wk/wv/wo)
// ---------------------------------------------------------------------------
#define WQ (C * C / 4)
__global__ void cvt_kernel(const float* __restrict__ wq, const float* __restrict__ wk,
                           const float* __restrict__ wv, const float* __restrict__ wo)
{
    int k = blockIdx.x * blockDim.x + threadIdx.x;
    if (k >= 4 * WQ) return;
    const float* src; __half* dst;
    if (k < 3 * WQ) { src = (k < WQ) ? wq : (k < 2 * WQ ? wk : wv); dst = &g_wh[k / WQ][0][0]; }
    else            { src = wo; dst = &g_wo[0][0]; }
    int j = (k % WQ) * 4;
    float4 v = *(const float4*)&src[j];
    __half2 h0 = __floats2half2_rn(v.x, v.y);
    __half2 h1 = __floats2half2_rn(v.z, v.w);
    *(uint2*)&dst[j] = make_uint2(*(unsigned*)&h0, *(unsigned*)&h1);
}

// ---------------------------------------------------------------------------
// Projection GEMM on tensor cores; converts fp32 X during the smem fill.
// V plane (plane==2) is stored with key-pairs permuted for LDS.64 frags.
// grid: (32, 2, 12)
// ---------------------------------------------------------------------------
__global__ __launch_bounds__(256) void projmma_kernel(const float* __restrict__ xs,
                                                      const float* __restrict__ xf,
                                                      const float* __restrict__ bq,
                                                      const float* __restrict__ bk,
                                                      const float* __restrict__ bv)
{
    int zz = blockIdx.z;
    int plane = zz % 3;
    int sb = zz / 3;
    int b = sb & 1;
    int src = sb >> 1;
    const __half* W = &g_wh[plane][0][0];
    const float* X32 = (src ? xf : xs) + (size_t)b * C * NN;
    const float* bias = (plane == 0) ? bq : (plane == 1) ? bk : bv;
    __half* Y = &g_qkv[src][b][plane][0][0];

    int o0 = blockIdx.y * 128;
    int n0 = blockIdx.x * 128;

    __shared__ __half Ws[128 * PSTRIDE];
    __shared__ __half Xs[128 * PSTRIDE];

    int t = threadIdx.x, lane = t & 31, w = t >> 5;
    int gr = lane >> 2, tc = lane & 3;
    int m_base = (w & 1) * 64;
    int n_base = (w >> 1) * 32;

    float acc[4][4][4] = {};

    for (int c0 = 0; c0 < C; c0 += 64) {
        __syncthreads();
        for (int i = t; i < 128 * 8; i += 256) {
            int r = i >> 3, cc = (i & 7) * 8;
            *(uint4*)&Ws[r * PSTRIDE + cc] =
                *(const uint4*)&W[(size_t)(o0 + r) * C + c0 + cc];
        }
        for (int i = t; i < 64 * 128; i += 256) {
            int kc = i >> 7, n = i & 127;
            Xs[n * PSTRIDE + kc] = __float2half(X32[(size_t)(c0 + kc) * NN + n0 + n]);
        }
        __syncthreads();

        #pragma unroll
        for (int ks = 0; ks < 4; ks++) {
            unsigned a[4][4];
            #pragma unroll
            for (int mi = 0; mi < 4; mi++) {
                const __half* r0 = &Ws[(m_base + mi * 16 + gr) * PSTRIDE + ks * 16 + 2 * tc];
                const __half* r1 = r0 + 8 * PSTRIDE;
                a[mi][0] = *(const unsigned*)&r0[0];
                a[mi][1] = *(const unsigned*)&r1[0];
                a[mi][2] = *(const unsigned*)&r0[8];
                a[mi][3] = *(const unsigned*)&r1[8];
            }
            #pragma unroll
            for (int ni = 0; ni < 4; ni++) {
                const __half* xr = &Xs[(n_base + ni * 8 + gr) * PSTRIDE + ks * 16 + 2 * tc];
                unsigned b0 = *(const unsigned*)&xr[0];
                unsigned b1 = *(const unsigned*)&xr[8];
                #pragma unroll
                for (int mi = 0; mi < 4; mi++)
                    mma_f16(acc[mi][ni], a[mi][0], a[mi][1], a[mi][2], a[mi][3], b0, b1);
            }
        }
    }

    #pragma unroll
    for (int mi = 0; mi < 4; mi++) {
        int r0 = o0 + m_base + mi * 16 + gr;
        int r1 = r0 + 8;
        float bi0 = bias[r0], bi1 = bias[r1];
        #pragma unroll
        for (int ni = 0; ni < 4; ni++) {
            int cb = n0 + n_base + ni * 8 + 2 * tc;
            // V plane: permute the half2 column-pair within its 16-key group
            int pairi = cb >> 1;
            int mm = pairi & 7;
            int qq = ((mm & 3) << 1) | (mm >> 2);
            int cb2 = ((pairi & ~7) | qq) << 1;
            int cbw = (plane == 2) ? cb2 : cb;
            __half2 h0 = __floats2half2_rn(acc[mi][ni][0] + bi0, acc[mi][ni][1] + bi0);
            __half2 h1 = __floats2half2_rn(acc[mi][ni][2] + bi1, acc[mi][ni][3] + bi1);
            *(__half2*)&Y[(size_t)r0 * NN + cbw] = h0;
            *(__half2*)&Y[(size_t)r1 * NN + cbw] = h1;
        }
    }
}

// ---------------------------------------------------------------------------
// Transpose Q and K planes per head: [d][n] -> [n][d-permuted].
// Q additionally pre-scaled by SCLOG2 (folds softmax scale into the mma).
// grid: (32, NH, 8)  z = src*4 + b*2 + plane
// ---------------------------------------------------------------------------
__global__ void tr_kernel()
{
    int z = blockIdx.z;
    int src = z >> 2, b = (z >> 1) & 1, plane = z & 1;
    int h = blockIdx.y;
    int n0 = blockIdx.x * 128;
    const __half* in = &g_qkv[src][b][plane][h * HD][0];
    __half* out = plane ? &g_kt[src][b][h][0][0] : &g_qt[src][b][h][0][0];
    const __half hs = __float2half(SCLOG2);

    __shared__ __half tile[32][136];
    int t = threadIdx.x;
    for (int i = t; i < 32 * 128; i += 256) {
        int d = i >> 7, n = i & 127;
        tile[d][n] = in[(size_t)d * NN + n0 + n];
    }
    __syncthreads();
    for (int i = t; i < 32 * 128; i += 256) {
        int d = i & 31, n = i >> 5;
        int dp = (d & 16) | pk16(d & 15);
        __half v = tile[d][n];
        if (plane == 0) v = __hmul(v, hs);
        out[(size_t)(n0 + n) * HD + dp] = v;
    }
}

// ---------------------------------------------------------------------------
// Flash attention: LDS.64 frag loads (permuted layouts), scale folded into Q,
// row sums via ones-mma, cp.async double buffering. 3 blocks/SM.
// grid: (32 qtiles, 8 heads, 4)
// ---------------------------------------------------------------------------
__global__ __launch_bounds__(256, 3) void attn_kernel()
{
    __shared__ __align__(16) char smbuf[2][STAGEHALF * 2];

    int qt = blockIdx.x;
    int h  = blockIdx.y;
    int zb = blockIdx.z;
    int b  = zb & 1, br = zb >> 1;
    int qsrc = br, ksrc = br ^ 1;

    const __half* Qt = &g_qt[qsrc][b][h][0][0];
    const __half* Kt = &g_kt[ksrc][b][h][0][0];
    const __half* V  = &g_qkv[ksrc][b][2][h * HD][0];
    __half* Out = &g_attn[br][b][h * HD][0];

    int t = threadIdx.x, lane = t & 31, w = t >> 5;
    int gr = lane >> 2, tc = lane & 3;
    int qb = w * 16;
    int n0 = qt * 128;

    // Q fragments from gmem (permuted layout: one uint2 per row per d-group)
    unsigned aq[2][4];
    {
        const __half* q0p = &Qt[(size_t)(n0 + qb + gr) * HD];
        const __half* q1p = &Qt[(size_t)(n0 + qb + gr + 8) * HD];
        #pragma unroll
        for (int kk = 0; kk < 2; kk++) {
            uint2 u = *(const uint2*)&q0p[kk * 16 + 4 * tc];
            uint2 v = *(const uint2*)&q1p[kk * 16 + 4 * tc];
            aq[kk][0] = u.x; aq[kk][2] = u.y;
            aq[kk][1] = v.x; aq[kk][3] = v.y;
        }
    }

    unsigned sbase = (unsigned)__cvta_generic_to_shared(&smbuf[0][0]);

    auto issue = [&](int kt, int st) {
        int k0 = kt * 128;
        unsigned sb = sbase + st * (STAGEHALF * 2);
        #pragma unroll
        for (int r = 0; r < 2; r++) {
            int i = t + r * 256, key = i >> 2, c = i & 3;
            cpa16(sb + (key * KSTRIDE + c * 8) * 2, Kt + (size_t)(k0 + key) * HD + c * 8);
        }
        #pragma unroll
        for (int r = 0; r < 2; r++) {
            int i = t + r * 256, d = i >> 4, c = i & 15;
            cpa16(sb + VOFFB + (d * VSTRIDE + c * 8) * 2, V + (size_t)d * NN + k0 + c * 8);
        }
        asm volatile("cp.async.commit_group;");
    };

    float o[4][4] = {};
    float lacc[4] = {};   // ones-mma row-sum accumulator: [0]=row gr, [2]=row gr+8

    issue(0, 0);

    for (int kt = 0; kt < 32; kt++) {
        if (kt < 31) {
            issue(kt + 1, (kt + 1) & 1);
            asm volatile("cp.async.wait_group 1;");
        } else {
            asm volatile("cp.async.wait_group 0;");
        }
        __syncthreads();

        const __half* Ks = (const __half*)&smbuf[kt & 1][0];
        const __half* Vs = Ks + 128 * KSTRIDE;

        #pragma unroll
        for (int ch = 0; ch < 8; ch++) {
            float s0[4] = {0.f, 0.f, 0.f, 0.f};
            float s1[4] = {0.f, 0.f, 0.f, 0.f};
            const __half* kr0 = &Ks[(ch * 16 + gr) * KSTRIDE];
            const __half* kr1 = kr0 + 8 * KSTRIDE;
            {
                uint2 b0 = *(const uint2*)&kr0[4 * tc];
                uint2 b1 = *(const uint2*)&kr0[16 + 4 * tc];
                mma_f16(s0, aq[0][0], aq[0][1], aq[0][2], aq[0][3], b0.x, b0.y);
                mma_f16(s0, aq[1][0], aq[1][1], aq[1][2], aq[1][3], b1.x, b1.y);
            }
            {
                uint2 b0 = *(const uint2*)&kr1[4 * tc];
                uint2 b1 = *(const uint2*)&kr1[16 + 4 * tc];
                mma_f16(s1, aq[0][0], aq[0][1], aq[0][2], aq[0][3], b0.x, b0.y);
                mma_f16(s1, aq[1][0], aq[1][1], aq[1][2], aq[1][3], b1.x, b1.y);
            }

            // p = exp2(s)  (scale already folded into Q)
            unsigned pa0 = hexp2_2(h2bits(s0[0], s0[1]));
            unsigned pa1 = hexp2_2(h2bits(s0[2], s0[3]));
            unsigned pa2 = hexp2_2(h2bits(s1[0], s1[1]));
            unsigned pa3 = hexp2_2(h2bits(s1[2], s1[3]));

            // row sums via ones-mma (full cross-lane reduction in f32 accum)
            mma_f16(lacc, pa0, pa1, pa2, pa3, ONESH2, ONESH2);

            #pragma unroll
            for (int dn = 0; dn < 4; dn++) {
                int d = dn * 8 + gr;
                uint2 bv = *(const uint2*)&Vs[d * VSTRIDE + ch * 16 + 4 * tc];
                mma_f16(o[dn], pa0, pa1, pa2, pa3, bv.x, bv.y);
            }
        }
        __syncthreads();
    }

    float li0 = 1.0f / lacc[0], li1 = 1.0f / lacc[2];

    // normalize + transpose via smem (reuse stage 0), coalesced store
    float* Os = (float*)&smbuf[0][0];
    #pragma unroll
    for (int dn = 0; dn < 4; dn++) {
        #pragma unroll
        for (int j = 0; j < 4; j++) {
            int d = dn * 8 + 2 * tc + (j & 1);
            int q = qb + gr + ((j >> 1) ? 8 : 0);
            Os[d * 132 + q] = o[dn][j] * ((j < 2) ? li0 : li1);
        }
    }
    __syncthreads();
    for (int i = t; i < 32 * 128; i += 256) {
        int d = i >> 7, q = i & 127;
        Out[(size_t)d * NN + n0 + q] = __float2half(Os[d * 132 + q]);
    }
}

// ---------------------------------------------------------------------------
// Output GEMM on tensor cores, 128(o) x 64(n) tiles:
// out = spatial + freq + 2*bo + wo @ (attn0 + attn1)
// grid: (64, 2, 2)
// ---------------------------------------------------------------------------
__global__ __launch_bounds__(256) void outmma_kernel(const float* __restrict__ xs,
                                                     const float* __restrict__ xf,
                                                     const float* __restrict__ bo,
                                                     float* __restrict__ out)
{
    int b  = blockIdx.z;
    int o0 = blockIdx.y * 128;
    int n0 = blockIdx.x * 64;
    const __half* a1 = &g_attn[0][b][0][0];
    const __half* a2 = &g_attn[1][b][0][0];

    __shared__ __half Ws[128 * PSTRIDE];
    __shared__ __half Xs[64 * PSTRIDE];

    int t = threadIdx.x, lane = t & 31, w = t >> 5;
    int gr = lane >> 2, tc = lane & 3;
    int m_base = (w & 1) * 64;
    int n_base = (w >> 1) * 16;

    float acc[4][2][4] = {};

    for (int c0 = 0; c0 < C; c0 += 64) {
        __syncthreads();
        for (int i = t; i < 128 * 8; i += 256) {
            int r = i >> 3, cc = (i & 7) * 8;
            *(uint4*)&Ws[r * PSTRIDE + cc] =
                *(const uint4*)&g_wo[o0 + r][c0 + cc];
        }
        for (int i = t; i < 64 * 64; i += 256) {
            int kc = i >> 6, n = i & 63;
            size_t off = (size_t)(c0 + kc) * NN + n0 + n;
            Xs[n * PSTRIDE + kc] =
                __float2half(__half2float(a1[off]) + __half2float(a2[off]));
        }
        __syncthreads();

        #pragma unroll
        for (int ks = 0; ks < 4; ks++) {
            unsigned a[4][4];
            #pragma unroll
            for (int mi = 0; mi < 4; mi++) {
                const __half* r0 = &Ws[(m_base + mi * 16 + gr) * PSTRIDE + ks * 16 + 2 * tc];
                const __half* r1 = r0 + 8 * PSTRIDE;
                a[mi][0] = *(const unsigned*)&r0[0];
                a[mi][1] = *(const unsigned*)&r1[0];
                a[mi][2] = *(const unsigned*)&r0[8];
                a[mi][3] = *(const unsigned*)&r1[8];
            }
            #pragma unroll
            for (int ni = 0; ni < 2; ni++) {
                const __half* xr = &Xs[(n_base + ni * 8 + gr) * PSTRIDE + ks * 16 + 2 * tc];
                unsigned b0 = *(const unsigned*)&xr[0];
                unsigned b1 = *(const unsigned*)&xr[8];
                #pragma unroll
                for (int mi = 0; mi < 4; mi++)
                    mma_f16(acc[mi][ni], a[mi][0], a[mi][1], a[mi][2], a[mi][3], b0, b1);
            }
        }
    }

    size_t base = (size_t)b * C * NN;
    #pragma unroll
    for (int mi = 0; mi < 4; mi++) {
        int r0 = o0 + m_base + mi * 16 + gr;
        int r1 = r0 + 8;
        float bi0 = 2.0f * bo[r0], bi1 = 2.0f * bo[r1];
        #pragma unroll
        for (int ni = 0; ni < 2; ni++) {
            int cb = n0 + n_base + ni * 8 + 2 * tc;
            size_t off0 = base + (size_t)r0 * NN + cb;
            size_t off1 = base + (size_t)r1 * NN + cb;
            float2 s0 = *(const float2*)&xs[off0];
            float2 f0 = *(const float2*)&xf[off0];
            float2 s1 = *(const float2*)&xs[off1];
            float2 f1 = *(const float2*)&xf[off1];
            float2 r;
            r.x = acc[mi][ni][0] + bi0 + s0.x + f0.x;
            r.y = acc[mi][ni][1] + bi0 + s0.y + f0.y;
            *(float2*)&out[off0] = r;
            r.x = acc[mi][ni][2] + bi1 + s1.x + f1.x;
            r.y = acc[mi][ni][3] + bi1 + s1.y + f1.y;
            *(float2*)&out[off1] = r;
        }
    }
}

extern "C" void kernel_launch(void* const* d_in, const int* in_sizes, int n_in,
                              void* d_out, int out_size)
{
    const float* xs = (const float*)d_in[0];
    const float* xf = (const float*)d_in[1];
    const float* wq = (const float*)d_in[2];
    const float* bq = (const float*)d_in[3];
    const float* wk = (const float*)d_in[4];
    const float* bk = (const float*)d_in[5];
    const float* wv = (const float*)d_in[6];
    const float* bv = (const float*)d_in[7];
    const float* wo = (const float*)d_in[8];
    const float* bo = (const float*)d_in[9];
    float* out = (float*)d_out;

    cvt_kernel<<<(4 * WQ + 255) / 256, 256>>>(wq, wk, wv, wo);
    projmma_kernel<<<dim3(32, 2, 12), 256>>>(xs, xf, bq, bk, bv);
    tr_kernel<<<dim3(32, NH, 8), 256>>>();
    attn_kernel<<<dim3(32, 8, 4), 256>>>();
    outmma_kernel<<<dim3(64, 2, 2), 256>>>(xs, xf, bo, out);
}